// round 14
// baseline (speedup 1.0000x reference)
#include <cuda_runtime.h>
#include <cuda_bf16.h>
#include <cuda_fp16.h>
#include <math.h>
#include <stdint.h>

#define NB 8
#define CINX 256
#define NCO 128
#define HH 64
#define WWD 64
#define HWX 4096
#define EPSV 1e-5f

__device__ __forceinline__ uint32_t smem_u32(const void* p) {
    uint32_t a;
    asm("{ .reg .u64 t; cvta.to.shared.u64 t, %1; cvt.u32.u64 %0, t; }" : "=r"(a) : "l"(p));
    return a;
}
__device__ __forceinline__ void ldsm4(uint32_t addr, uint32_t r[4]) {
    asm volatile("ldmatrix.sync.aligned.m8n8.x4.shared.b16 {%0,%1,%2,%3},[%4];"
                 : "=r"(r[0]), "=r"(r[1]), "=r"(r[2]), "=r"(r[3]) : "r"(addr));
}
__device__ __forceinline__ void mma16816(float d[4], const uint32_t a[4], const uint32_t b0,
                                         const uint32_t b1) {
    asm volatile("mma.sync.aligned.m16n8k16.row.col.f32.bf16.bf16.f32 "
                 "{%0,%1,%2,%3},{%4,%5,%6,%7},{%8,%9},{%0,%1,%2,%3};"
                 : "+f"(d[0]), "+f"(d[1]), "+f"(d[2]), "+f"(d[3])
                 : "r"(a[0]), "r"(a[1]), "r"(a[2]), "r"(a[3]), "r"(b0), "r"(b1));
}
__device__ __forceinline__ void mma16816h(float d[4], const uint32_t a[4], const uint32_t b0,
                                          const uint32_t b1) {
    asm volatile("mma.sync.aligned.m16n8k16.row.col.f32.f16.f16.f32 "
                 "{%0,%1,%2,%3},{%4,%5,%6,%7},{%8,%9},{%0,%1,%2,%3};"
                 : "+f"(d[0]), "+f"(d[1]), "+f"(d[2]), "+f"(d[3])
                 : "r"(a[0]), "r"(a[1]), "r"(a[2]), "r"(a[3]), "r"(b0), "r"(b1));
}
__device__ __forceinline__ uint32_t packsplit(float v0, float v1, uint32_t& lo) {
    __nv_bfloat16 h0 = __float2bfloat16(v0), h1 = __float2bfloat16(v1);
    __nv_bfloat16 l0 = __float2bfloat16(v0 - __bfloat162float(h0));
    __nv_bfloat16 l1 = __float2bfloat16(v1 - __bfloat162float(h1));
    lo = (uint32_t)__bfloat16_as_ushort(l0) | ((uint32_t)__bfloat16_as_ushort(l1) << 16);
    return (uint32_t)__bfloat16_as_ushort(h0) | ((uint32_t)__bfloat16_as_ushort(h1) << 16);
}
__device__ __forceinline__ uint32_t packh2(float a, float b) {
    __half2 h = __floats2half2_rn(a, b);
    return *(uint32_t*)&h;
}
#define CP_ASYNC16(s, g) asm volatile("cp.async.cg.shared.global [%0], [%1], 16;" ::"r"(s), "l"(g) : "memory")
#define CP_COMMIT() asm volatile("cp.async.commit_group;" ::: "memory")
#define CP_WAIT1() asm volatile("cp.async.wait_group 1;" ::: "memory")
#define CP_WAIT0() asm volatile("cp.async.wait_group 0;" ::: "memory")

// -------- scratch --------
static __device__ float g_om[NB * 27 * HWX];
static __device__ float g_xt[NB * HWX * CINX];
static __device__ __align__(16) __half g_xth[NB * HWX * CINX];
static __device__ __align__(16) __half g_out1th[NB * HWX * NCO];
static __device__ float g_stats1[2 * NCO];
static __device__ float g_stats2[2 * NCO];
static __device__ float g_p1[256 * 128 * 2];
static __device__ float g_p2[1024 * 128 * 2];
static __device__ __align__(16) __nv_bfloat16 g_k1Ahi[36 * 2304], g_k1Alo[36 * 2304];
static __device__ __align__(16) __half g_k2Ah[36 * 9216];
static __device__ __align__(16) __half g_k4Ah[32 * 9216];

// -------- K0: weight prep --------
__global__ void k0_prep(const float* __restrict__ w_dcn, const float* __restrict__ w_off,
                        const float* __restrict__ w_ct) {
    const int N_K1 = 36 * 2048, N_K2 = 128 * 256 * 9, N_K4 = 262144;
    const int ntot = N_K1 + N_K2 + N_K4;
    for (int idx = blockIdx.x * blockDim.x + threadIdx.x; idx < ntot; idx += gridDim.x * blockDim.x) {
        if (idx < N_K1) {
            const int st = idx >> 11, o = (idx >> 6) & 31, kk = idx & 63;
            const int c = (st & 3) * 64 + kk, j = st >> 2;
            const float w = (o < 27) ? w_off[(o * CINX + c) * 9 + j] : 0.f;
            const __nv_bfloat16 hi = __float2bfloat16(w);
            g_k1Ahi[st * 2304 + o * 72 + kk] = hi;
            g_k1Alo[st * 2304 + o * 72 + kk] = __float2bfloat16(w - __bfloat162float(hi));
        } else if (idx < N_K1 + N_K2) {
            const int r = idx - N_K1, o = r & 127, c = (r >> 7) & 255, k = r >> 15;
            const float w = w_dcn[(o * CINX + c) * 9 + k];
            const int st = r >> 13, kk = (r >> 7) & 63;
            g_k2Ah[st * 9216 + o * 72 + kk] = __float2half(w);
        } else {
            const int r2 = idx - N_K1 - N_K2;
            const int o = r2 & 127, c = (r2 >> 7) & 127, j = (r2 >> 14) & 7, P = r2 >> 17;
            const int wdh = P + 2 * (j >> 2), wdw = j & 3;
            const float w = w_ct[(c * NCO + o) * 16 + (3 - wdh) * 4 + (3 - wdw)];
            const int st = j * 2 + (c >> 6), kk = c & 63;
            g_k4Ah[(P * 16 + st) * 9216 + o * 72 + kk] = __float2half(w);
        }
    }
}

// -------- kT: x NCHW -> NHWC (fp32 + fp16) --------
__global__ void kT_transpose(const float* __restrict__ x) {
    __shared__ float tile[32][33];
    const int b = blockIdx.z;
    const int cb = blockIdx.y * 32, hb = blockIdx.x * 32;
    const int tx = threadIdx.x & 31, ty = threadIdx.x >> 5;
    const float* xb = x + ((size_t)b * CINX + cb) * HWX + hb;
#pragma unroll
    for (int i = 0; i < 32; i += 8) tile[ty + i][tx] = xb[(size_t)(ty + i) * HWX + tx];
    __syncthreads();
    float* xo = g_xt + ((size_t)b * HWX + hb) * CINX + cb;
    __half* xoh = g_xth + ((size_t)b * HWX + hb) * CINX + cb;
#pragma unroll
    for (int i = 0; i < 32; i += 8) {
        const float v = tile[tx][ty + i];
        xo[(size_t)(ty + i) * CINX + tx] = v;
        xoh[(size_t)(ty + i) * CINX + tx] = __float2half(v);
    }
}

// -------- K1: offset conv, pipelined mma, bf16x3 (R11-proven) --------
#define K1_SMEM 55296
__global__ __launch_bounds__(256) void k1_off_mma(const float* __restrict__ b_off) {
    extern __shared__ char sm[];
    const uint32_t sb = smem_u32(sm);
    const int b = blockIdx.x >> 6, h = blockIdx.x & 63, t = threadIdx.x;
    const int px = t >> 2, qq = t & 3;
    const int w = t >> 5, L = t & 31;
    const int m0 = (w & 1) * 16, n0 = (w >> 1) * 16;
    const uint32_t aAb = sb + (m0 + (L & 15)) * 144 + ((L & 16) ? 16 : 0);
    const uint32_t aBb = sb + 18432 + (n0 + (L & 7) + ((L & 16) ? 8 : 0)) * 144 + ((L & 8) ? 16 : 0);
    const float* xtb = g_xt + (size_t)b * HWX * CINX;

    float acc[2][4];
#pragma unroll
    for (int i = 0; i < 2; i++)
#pragma unroll
        for (int q = 0; q < 4; q++) acc[i][q] = 0.f;

    float4 raw0, raw1, raw2, raw3;
    bool rok;
    {
        const uint4* gh = (const uint4*)g_k1Ahi;
        const uint4* gl = (const uint4*)g_k1Alo;
        for (int i = t; i < 288; i += 256) {
            CP_ASYNC16(sb + i * 16, gh + i);
            CP_ASYNC16(sb + 4608 + i * 16, gl + i);
        }
        CP_COMMIT();
        const int row = h - 1, col = px - 1;
        rok = (row >= 0) && (col >= 0) && (col < WWD);
        if (rok) {
            const float4* sp = (const float4*)(xtb + ((size_t)row * 64 + col) * CINX + qq * 16);
            raw0 = sp[0]; raw1 = sp[1]; raw2 = sp[2]; raw3 = sp[3];
        }
    }

    for (int s = 0; s < 36; ++s) {
        const int buf = s & 1;
        {
            float v[16];
            if (rok) {
                const float4 rr[4] = {raw0, raw1, raw2, raw3};
#pragma unroll
                for (int j2 = 0; j2 < 4; j2++) {
                    v[j2 * 4 + 0] = rr[j2].x; v[j2 * 4 + 1] = rr[j2].y;
                    v[j2 * 4 + 2] = rr[j2].z; v[j2 * 4 + 3] = rr[j2].w;
                }
            } else {
#pragma unroll
                for (int z = 0; z < 16; z++) v[z] = 0.f;
            }
            uint32_t hw_[8], lw_[8];
#pragma unroll
            for (int i = 0; i < 8; i++) hw_[i] = packsplit(v[2 * i], v[2 * i + 1], lw_[i]);
            char* Bp = sm + 18432 + buf * 18432 + px * 144 + qq * 32;
            ((uint4*)Bp)[0] = make_uint4(hw_[0], hw_[1], hw_[2], hw_[3]);
            ((uint4*)Bp)[1] = make_uint4(hw_[4], hw_[5], hw_[6], hw_[7]);
            ((uint4*)(Bp + 9216))[0] = make_uint4(lw_[0], lw_[1], lw_[2], lw_[3]);
            ((uint4*)(Bp + 9216))[1] = make_uint4(lw_[4], lw_[5], lw_[6], lw_[7]);
        }
        __syncthreads();
        const bool more = (s + 1 < 36);
        if (more) {
            const int sn = s + 1;
            const uint4* gh = ((const uint4*)g_k1Ahi) + sn * 288;
            const uint4* gl = ((const uint4*)g_k1Alo) + sn * 288;
            const uint32_t dA = sb + (sn & 1) * 9216;
            for (int i = t; i < 288; i += 256) {
                CP_ASYNC16(dA + i * 16, gh + i);
                CP_ASYNC16(dA + 4608 + i * 16, gl + i);
            }
            CP_COMMIT();
            CP_WAIT1();
            const int j = sn >> 2, c0 = (sn & 3) * 64;
            const int jy = j / 3, jx = j - jy * 3;
            const int row = h - 1 + jy, col = px - 1 + jx;
            rok = (row >= 0) && (row < HH) && (col >= 0) && (col < WWD);
            if (rok) {
                const float4* sp = (const float4*)(xtb + ((size_t)row * 64 + col) * CINX + c0 + qq * 16);
                raw0 = sp[0]; raw1 = sp[1]; raw2 = sp[2]; raw3 = sp[3];
            }
        } else {
            CP_WAIT0();
        }
        const uint32_t aA = aAb + buf * 9216;
        const uint32_t aB = aBb + buf * 18432;
#pragma unroll
        for (int ks = 0; ks < 4; ks++) {
            const uint32_t kb = ks * 32;
            uint32_t ah[4], al[4], bh[4], bl[4];
            ldsm4(aA + kb, ah);
            ldsm4(aA + 4608 + kb, al);
            ldsm4(aB + kb, bh);
            ldsm4(aB + 9216 + kb, bl);
#pragma unroll
            for (int tn = 0; tn < 2; tn++) {
                mma16816(acc[tn], ah, bh[tn * 2], bh[tn * 2 + 1]);
                mma16816(acc[tn], ah, bl[tn * 2], bl[tn * 2 + 1]);
                mma16816(acc[tn], al, bh[tn * 2], bh[tn * 2 + 1]);
            }
        }
    }
    const int o = m0 + (L >> 2);
#pragma unroll
    for (int tn = 0; tn < 2; tn++) {
        const int pc = n0 + tn * 8 + (L & 3) * 2;
        if (o < 27) {
            const float bv = b_off[o];
            float2 v = {acc[tn][0] + bv, acc[tn][1] + bv};
            *(float2*)(g_om + (((size_t)b * 27 + o) * 64 + h) * 64 + pc) = v;
        }
        if (o + 8 < 27) {
            const float bv = b_off[o + 8];
            float2 v = {acc[tn][2] + bv, acc[tn][3] + bv};
            *(float2*)(g_om + (((size_t)b * 27 + o + 8) * 64 + h) * 64 + pc) = v;
        }
    }
}

// -------- K2: DCN, fp16 gather, M128xN128, 512 threads (R11-proven) --------
#define K2_SMEM 73728
__device__ __forceinline__ void bilin2(int b, int row, int col, int T, int* pidx, float* pwgt) {
    const float oy = g_om[((b * 27 + T) * 64 + row) * 64 + col];
    const float ox = g_om[((b * 27 + 9 + T) * 64 + row) * 64 + col];
    const float mm = g_om[((b * 27 + 18 + T) * 64 + row) * 64 + col];
    const float mask = 1.0f / (1.0f + expf(-mm));
    const float py = oy + (float)(row - 1 + T / 3);
    const float pxx = ox + (float)(col - 1 + T % 3);
    const float y0f = floorf(py), x0f = floorf(pxx);
    const int y0 = (int)y0f, x0 = (int)x0f;
    const float ly = py - y0f, lx = pxx - x0f;
#pragma unroll
    for (int q = 0; q < 4; q++) {
        const int yi = y0 + (q >> 1), xi = x0 + (q & 1);
        const bool valid = (yi >= 0) && (yi < HH) && (xi >= 0) && (xi < WWD);
        pidx[q] = min(max(yi, 0), HH - 1) * WWD + min(max(xi, 0), WWD - 1);
        const float wq = ((q >> 1) ? ly : 1.f - ly) * ((q & 1) ? lx : 1.f - lx);
        pwgt[q] = valid ? wq * mask : 0.f;
    }
}
__device__ __forceinline__ void acc_h16(float* v, uint4 ha, uint4 hb, float wq) {
    const __half2* pa = (const __half2*)&ha;
    const __half2* pb = (const __half2*)&hb;
#pragma unroll
    for (int i = 0; i < 4; i++) {
        const float2 f = __half22float2(pa[i]);
        v[2 * i] += wq * f.x; v[2 * i + 1] += wq * f.y;
    }
#pragma unroll
    for (int i = 0; i < 4; i++) {
        const float2 f = __half22float2(pb[i]);
        v[8 + 2 * i] += wq * f.x; v[8 + 2 * i + 1] += wq * f.y;
    }
}

__global__ __launch_bounds__(512, 1) void k2_dcn_mma(const float* __restrict__ b_dcn) {
    extern __shared__ char sm[];
    const uint32_t sb = smem_u32(sm);
    const int b = blockIdx.x >> 5, H = blockIdx.x & 31, t = threadIdx.x;
    const __half* xtb = g_xth + (size_t)b * HWX * CINX;
    const int px = t >> 2, qq = t & 3;
    const int row = 2 * H + (px >> 6), col = px & 63;
    const int w = t >> 5, L = t & 31;
    const int m0 = (w & 3) * 32, n0 = (w >> 2) * 32;
    const uint32_t aAb = sb + (m0 + (L & 15)) * 144 + ((L & 16) ? 16 : 0);
    const uint32_t aBb = sb + 36864 + (n0 + (L & 7) + ((L & 16) ? 8 : 0)) * 144 + ((L & 8) ? 16 : 0);

    float acc[2][4][4];
#pragma unroll
    for (int i = 0; i < 2; i++)
#pragma unroll
        for (int j = 0; j < 4; j++)
#pragma unroll
            for (int q = 0; q < 4; q++) acc[i][j][q] = 0.f;

    int pidx[4];
    float pwgt[4];
    float v[16];
    {
        const uint4* gh = (const uint4*)g_k2Ah;
        for (int i = t; i < 1152; i += 512) CP_ASYNC16(sb + i * 16, gh + i);
        CP_COMMIT();
        bilin2(b, row, col, 0, pidx, pwgt);
#pragma unroll
        for (int i = 0; i < 16; i++) v[i] = 0.f;
#pragma unroll
        for (int cn = 0; cn < 4; cn++) {
            const uint4* sp = (const uint4*)(xtb + (size_t)pidx[cn] * CINX + qq * 16);
            acc_h16(v, sp[0], sp[1], pwgt[cn]);
        }
    }

    for (int s = 0; s < 36; ++s) {
        const int buf = s & 1;
        {
            uint32_t hw_[8];
#pragma unroll
            for (int i = 0; i < 8; i++) hw_[i] = packh2(v[2 * i], v[2 * i + 1]);
            char* Bp = sm + 36864 + buf * 18432 + px * 144 + qq * 32;
            ((uint4*)Bp)[0] = make_uint4(hw_[0], hw_[1], hw_[2], hw_[3]);
            ((uint4*)Bp)[1] = make_uint4(hw_[4], hw_[5], hw_[6], hw_[7]);
        }
        __syncthreads();
        const bool more = (s + 1 < 36);
        const __half* gbase = xtb;
        if (more) {
            const uint4* gh = ((const uint4*)g_k2Ah) + (s + 1) * 1152;
            const uint32_t dA = sb + ((s + 1) & 1) * 18432;
            for (int i = t; i < 1152; i += 512) CP_ASYNC16(dA + i * 16, gh + i);
            CP_COMMIT();
            CP_WAIT1();
            if (((s + 1) & 3) == 0) bilin2(b, row, col, (s + 1) >> 2, pidx, pwgt);
            gbase = xtb + ((s + 1) & 3) * 64 + qq * 16;
#pragma unroll
            for (int i = 0; i < 16; i++) v[i] = 0.f;
        } else {
            CP_WAIT0();
        }
        const uint32_t aA = aAb + buf * 18432;
        const uint32_t aB = aBb + buf * 18432;
        uint4 ra, rb;
        if (more) {
            const uint4* sp = (const uint4*)(gbase + (size_t)pidx[0] * CINX);
            ra = sp[0]; rb = sp[1];
        }
#pragma unroll
        for (int ks = 0; ks < 4; ks++) {
            const uint32_t kb = ks * 32;
            uint32_t ah[2][4], bh[2][4];
            ldsm4(aA + kb, ah[0]);
            ldsm4(aA + 2304 + kb, ah[1]);
            ldsm4(aB + kb, bh[0]);
            ldsm4(aB + 2304 + kb, bh[1]);
#pragma unroll
            for (int tm = 0; tm < 2; tm++)
#pragma unroll
                for (int tn = 0; tn < 4; tn++) {
                    const uint32_t* BH = &bh[tn >> 1][(tn & 1) * 2];
                    mma16816h(acc[tm][tn], ah[tm], BH[0], BH[1]);
                }
            if (more) {
                acc_h16(v, ra, rb, pwgt[ks]);
                if (ks < 3) {
                    const uint4* sp = (const uint4*)(gbase + (size_t)pidx[ks + 1] * CINX);
                    ra = sp[0]; rb = sp[1];
                }
            }
        }
    }
    // epilogue: half NHWC out1t + BN1 partials
    float* red = (float*)(sm + 36864);
    const int ng = w >> 2;
#pragma unroll
    for (int tm = 0; tm < 2; tm++) {
        const int o = m0 + tm * 16 + (L >> 2);
        const float bv0 = b_dcn[o], bv1 = b_dcn[o + 8];
        float so = 0.f, qo = 0.f, s8 = 0.f, q8 = 0.f;
#pragma unroll
        for (int tn = 0; tn < 4; tn++) {
            const int pc = n0 + tn * 8 + (L & 3) * 2;
            __half* base = g_out1th + ((size_t)b * HWX + H * 128 + pc) * NCO + o;
            const float v0 = acc[tm][tn][0] + bv0, v1 = acc[tm][tn][1] + bv0;
            const float v2 = acc[tm][tn][2] + bv1, v3 = acc[tm][tn][3] + bv1;
            base[0] = __float2half(v0); base[NCO] = __float2half(v1);
            base[8] = __float2half(v2); base[NCO + 8] = __float2half(v3);
            so += v0 + v1; qo += v0 * v0 + v1 * v1;
            s8 += v2 + v3; q8 += v2 * v2 + v3 * v3;
        }
#pragma unroll
        for (int d = 1; d < 4; d <<= 1) {
            so += __shfl_xor_sync(0xFFFFFFFF, so, d);
            qo += __shfl_xor_sync(0xFFFFFFFF, qo, d);
            s8 += __shfl_xor_sync(0xFFFFFFFF, s8, d);
            q8 += __shfl_xor_sync(0xFFFFFFFF, q8, d);
        }
        if ((L & 3) == 0) {
            red[(ng * 128 + o) * 2] = so;
            red[(ng * 128 + o) * 2 + 1] = qo;
            red[(ng * 128 + o + 8) * 2] = s8;
            red[(ng * 128 + o + 8) * 2 + 1] = q8;
        }
    }
    __syncthreads();
    if (t < 128) {
        float ss = 0.f, qs = 0.f;
#pragma unroll
        for (int g = 0; g < 4; g++) {
            ss += red[(g * 128 + t) * 2];
            qs += red[(g * 128 + t) * 2 + 1];
        }
        g_p1[(blockIdx.x * 128 + t) * 2] = ss;
        g_p1[(blockIdx.x * 128 + t) * 2 + 1] = qs;
    }
}

// -------- BN finalize --------
__device__ __forceinline__ void fin_body(const float* part, int nblk, float nelem,
                                         const float* gamma, const float* beta, float* stats) {
    const int ch = blockIdx.x, t = threadIdx.x;
    float s = 0.f, q = 0.f;
    for (int i = t; i < nblk; i += 256) {
        s += part[(i * 128 + ch) * 2];
        q += part[(i * 128 + ch) * 2 + 1];
    }
    __shared__ float rs[256], rq[256];
    rs[t] = s; rq[t] = q;
    __syncthreads();
    for (int off = 128; off > 0; off >>= 1) {
        if (t < off) { rs[t] += rs[t + off]; rq[t] += rq[t + off]; }
        __syncthreads();
    }
    if (t == 0) {
        const float mean = rs[0] / nelem;
        const float var = rq[0] / nelem - mean * mean;
        const float sc = rsqrtf(var + EPSV) * gamma[ch];
        stats[ch] = sc;
        stats[NCO + ch] = beta[ch] - mean * sc;
    }
}
__global__ void k3b_fin(const float* __restrict__ g, const float* __restrict__ b) {
    fin_body(g_p1, 256, (float)(NB * HWX), g, b, g_stats1);
}
__global__ void k5b_fin(const float* __restrict__ g, const float* __restrict__ b) {
    fin_body(g_p2, 1024, (float)(NB * 16384), g, b, g_stats2);
}

// -------- K4: tconv, Y-pair merged, M128xN128, 512 threads --------
// smem: A0@0 (18432), A1@18432, B0@36864 (18432), B1@55296, sStats@73728 (1024). total 74752.
#define K4_SMEM 74752
__device__ __forceinline__ int k4_st(int s, int p) {
    const int r = s >> 2, dwi = (s >> 1) & 1, ch = s & 1;
    return (r * 4 + p + 2 * dwi) * 2 + ch;
}
__global__ __launch_bounds__(512, 1) void k4_tconv_mma(float* __restrict__ out2) {
    extern __shared__ char sm[];
    const uint32_t sb = smem_u32(sm);
    const int b = blockIdx.x >> 7, j = (blockIdx.x >> 1) & 63, p = blockIdx.x & 1;
    const int Ya = (j >> 1) * 4 + (j & 1);  // pair rows: Ya, Ya+2 (same parity)
    const int Ypar = Ya & 1;
    const int y0ra = (Ya - 2 + Ypar) / 2;
    const int t = threadIdx.x;
    float* sStats = (float*)(sm + 73728);
    const int px = t >> 2, qq = t & 3;
    const int sub = px >> 6, ii = px & 63;
    const int w = t >> 5, L = t & 31;
    const int m0 = (w & 3) * 32, n0 = (w >> 2) * 32;
    const uint32_t aAb = sb + (m0 + (L & 15)) * 144 + ((L & 16) ? 16 : 0);
    const uint32_t aBb = sb + 36864 + (n0 + (L & 7) + ((L & 16) ? 8 : 0)) * 144 + ((L & 8) ? 16 : 0);

    if (t < 256) sStats[t] = g_stats1[t];

    float acc[2][4][4];
#pragma unroll
    for (int i = 0; i < 2; i++)
#pragma unroll
        for (int jj = 0; jj < 4; jj++)
#pragma unroll
            for (int q = 0; q < 4; q++) acc[i][jj][q] = 0.f;

    uint4 ra, rb;
    bool rok;
    int rcnx;
    {
        const int st0 = k4_st(0, p);
        const uint4* gh = ((const uint4*)g_k4Ah) + (Ypar * 16 + st0) * 1152;
        for (int i = t; i < 1152; i += 512) CP_ASYNC16(sb + i * 16, gh + i);
        CP_COMMIT();
        const int yrow = y0ra + sub, gx = ii + p - 1;
        rcnx = qq * 16;
        rok = (yrow >= 0) && (yrow < HH) && (gx >= 0) && (gx < WWD);
        if (rok) {
            const uint4* sp = (const uint4*)(g_out1th + ((size_t)b * HWX + yrow * 64 + gx) * NCO + rcnx);
            ra = sp[0]; rb = sp[1];
        }
    }
    __syncthreads();  // sStats visible

    for (int s = 0; s < 8; ++s) {
        const int buf = s & 1;
        {
            float v[16];
            if (rok) {
                const __half2* pa = (const __half2*)&ra;
                const __half2* pb = (const __half2*)&rb;
#pragma unroll
                for (int j2 = 0; j2 < 4; j2++) {
                    const float2 f = __half22float2(pa[j2]);
                    const int c = rcnx + j2 * 2;
                    v[j2 * 2 + 0] = fmaxf(0.f, fmaf(f.x, sStats[c + 0], sStats[128 + c + 0]));
                    v[j2 * 2 + 1] = fmaxf(0.f, fmaf(f.y, sStats[c + 1], sStats[128 + c + 1]));
                }
#pragma unroll
                for (int j2 = 0; j2 < 4; j2++) {
                    const float2 f = __half22float2(pb[j2]);
                    const int c = rcnx + 8 + j2 * 2;
                    v[8 + j2 * 2 + 0] = fmaxf(0.f, fmaf(f.x, sStats[c + 0], sStats[128 + c + 0]));
                    v[8 + j2 * 2 + 1] = fmaxf(0.f, fmaf(f.y, sStats[c + 1], sStats[128 + c + 1]));
                }
            } else {
#pragma unroll
                for (int z = 0; z < 16; z++) v[z] = 0.f;
            }
            uint32_t hw_[8];
#pragma unroll
            for (int i = 0; i < 8; i++) hw_[i] = packh2(v[2 * i], v[2 * i + 1]);
            char* Bp = sm + 36864 + buf * 18432 + px * 144 + qq * 32;
            ((uint4*)Bp)[0] = make_uint4(hw_[0], hw_[1], hw_[2], hw_[3]);
            ((uint4*)Bp)[1] = make_uint4(hw_[4], hw_[5], hw_[6], hw_[7]);
        }
        __syncthreads();
        const bool more = (s + 1 < 8);
        if (more) {
            const int stn = k4_st(s + 1, p);
            const uint4* gh = ((const uint4*)g_k4Ah) + (Ypar * 16 + stn) * 1152;
            const uint32_t dA = sb + ((s + 1) & 1) * 18432;
            for (int i = t; i < 1152; i += 512) CP_ASYNC16(dA + i * 16, gh + i);
            CP_COMMIT();
            CP_WAIT1();
            const int sn = s + 1;
            const int r = sn >> 2, dwi = (sn >> 1) & 1, ch = sn & 1;
            const int yrow = y0ra + sub + r, gx = ii + p + dwi - 1;
            rcnx = ch * 64 + qq * 16;
            rok = (yrow >= 0) && (yrow < HH) && (gx >= 0) && (gx < WWD);
            if (rok) {
                const uint4* sp = (const uint4*)(g_out1th + ((size_t)b * HWX + yrow * 64 + gx) * NCO + rcnx);
                ra = sp[0]; rb = sp[1];
            }
        } else {
            CP_WAIT0();
        }
        const uint32_t aA = aAb + buf * 18432;
        const uint32_t aB = aBb + buf * 18432;
#pragma unroll
        for (int ks = 0; ks < 4; ks++) {
            const uint32_t kb = ks * 32;
            uint32_t ah[2][4], bh[2][4];
            ldsm4(aA + kb, ah[0]);
            ldsm4(aA + 2304 + kb, ah[1]);
            ldsm4(aB + kb, bh[0]);
            ldsm4(aB + 2304 + kb, bh[1]);
#pragma unroll
            for (int tm = 0; tm < 2; tm++)
#pragma unroll
                for (int tn = 0; tn < 4; tn++) {
                    const uint32_t* BH = &bh[tn >> 1][(tn & 1) * 2];
                    mma16816h(acc[tm][tn], ah[tm], BH[0], BH[1]);
                }
        }
    }
    // epilogue: write out2 + BN2 partials
    float* red = (float*)(sm + 36864);
    const int ng = w >> 2;
#pragma unroll
    for (int tm = 0; tm < 2; tm++) {
        const int o = m0 + tm * 16 + (L >> 2);
        float so = 0.f, qo = 0.f, s8 = 0.f, q8 = 0.f;
#pragma unroll
        for (int tn = 0; tn < 4; tn++) {
            const int ic = n0 + tn * 8 + (L & 3) * 2;
            const int sub2 = ic >> 6, ipx = ic & 63;
            const int X = 2 * ipx + p;
            const int Y = Ya + 2 * sub2;
            float* base = out2 + (((size_t)b * NCO + o) * 128 + Y) * 128 + X;
            const float v0 = acc[tm][tn][0], v1 = acc[tm][tn][1];
            const float v2 = acc[tm][tn][2], v3 = acc[tm][tn][3];
            base[0] = v0; base[2] = v1;
            base[8 * 16384] = v2; base[8 * 16384 + 2] = v3;
            so += v0 + v1; qo += v0 * v0 + v1 * v1;
            s8 += v2 + v3; q8 += v2 * v2 + v3 * v3;
        }
#pragma unroll
        for (int d = 1; d < 4; d <<= 1) {
            so += __shfl_xor_sync(0xFFFFFFFF, so, d);
            qo += __shfl_xor_sync(0xFFFFFFFF, qo, d);
            s8 += __shfl_xor_sync(0xFFFFFFFF, s8, d);
            q8 += __shfl_xor_sync(0xFFFFFFFF, q8, d);
        }
        if ((L & 3) == 0) {
            red[(ng * 128 + o) * 2] = so;
            red[(ng * 128 + o) * 2 + 1] = qo;
            red[(ng * 128 + o + 8) * 2] = s8;
            red[(ng * 128 + o + 8) * 2 + 1] = q8;
        }
    }
    __syncthreads();
    if (t < 128) {
        float ss = 0.f, qs = 0.f;
#pragma unroll
        for (int g = 0; g < 4; g++) {
            ss += red[(g * 128 + t) * 2];
            qs += red[(g * 128 + t) * 2 + 1];
        }
        g_p2[(blockIdx.x * 128 + t) * 2] = ss;
        g_p2[(blockIdx.x * 128 + t) * 2 + 1] = qs;
    }
}

// -------- K6: in-place BN2+ReLU --------
__global__ void k6_bnrelu(float* __restrict__ out) {
    const int n4 = NB * NCO * 128 * 128 / 4;
    int i4 = blockIdx.x * blockDim.x + threadIdx.x;
    if (i4 < n4) {
        float4 v = ((float4*)out)[i4];
        const int ch = (i4 >> 12) & 127;
        const float sc = g_stats2[ch], sh = g_stats2[NCO + ch];
        v.x = fmaxf(0.f, fmaf(v.x, sc, sh));
        v.y = fmaxf(0.f, fmaf(v.y, sc, sh));
        v.z = fmaxf(0.f, fmaf(v.z, sc, sh));
        v.w = fmaxf(0.f, fmaf(v.w, sc, sh));
        ((float4*)out)[i4] = v;
    }
}

extern "C" void kernel_launch(void* const* d_in, const int* in_sizes, int n_in,
                              void* d_out, int out_size) {
    const float* x = (const float*)d_in[0];
    const float* w_off = (const float*)d_in[1];
    const float* b_off = (const float*)d_in[2];
    const float* w_dcn = (const float*)d_in[3];
    const float* b_dcn = (const float*)d_in[4];
    const float* gamma1 = (const float*)d_in[5];
    const float* beta1 = (const float*)d_in[6];
    const float* w_ct = (const float*)d_in[7];
    const float* gamma2 = (const float*)d_in[8];
    const float* beta2 = (const float*)d_in[9];
    float* out = (float*)d_out;
    (void)in_sizes; (void)n_in; (void)out_size;

    static int attr_done = 0;
    if (!attr_done) {
        cudaFuncSetAttribute(k1_off_mma, cudaFuncAttributeMaxDynamicSharedMemorySize, K1_SMEM);
        cudaFuncSetAttribute(k2_dcn_mma, cudaFuncAttributeMaxDynamicSharedMemorySize, K2_SMEM);
        cudaFuncSetAttribute(k4_tconv_mma, cudaFuncAttributeMaxDynamicSharedMemorySize, K4_SMEM);
        attr_done = 1;
    }
    k0_prep<<<256, 256>>>(w_dcn, w_off, w_ct);
    kT_transpose<<<dim3(128, 8, 8), 256>>>(x);
    k1_off_mma<<<NB * HH, 256, K1_SMEM>>>(b_off);
    k2_dcn_mma<<<NB * 32, 512, K2_SMEM>>>(b_dcn);
    k3b_fin<<<NCO, 256>>>(gamma1, beta1);
    k4_tconv_mma<<<NB * 128, 512, K4_SMEM>>>(out);
    k5b_fin<<<NCO, 256>>>(gamma2, beta2);
    k6_bnrelu<<<(NB * NCO * 128 * 128 / 4 + 255) / 256, 256>>>(out);
}

// round 15
// speedup vs baseline: 1.0799x; 1.0799x over previous
#include <cuda_runtime.h>
#include <cuda_bf16.h>
#include <cuda_fp16.h>
#include <math.h>
#include <stdint.h>

#define NB 8
#define CINX 256
#define NCO 128
#define HH 64
#define WWD 64
#define HWX 4096
#define EPSV 1e-5f

__device__ __forceinline__ uint32_t smem_u32(const void* p) {
    uint32_t a;
    asm("{ .reg .u64 t; cvta.to.shared.u64 t, %1; cvt.u32.u64 %0, t; }" : "=r"(a) : "l"(p));
    return a;
}
__device__ __forceinline__ void ldsm4(uint32_t addr, uint32_t r[4]) {
    asm volatile("ldmatrix.sync.aligned.m8n8.x4.shared.b16 {%0,%1,%2,%3},[%4];"
                 : "=r"(r[0]), "=r"(r[1]), "=r"(r[2]), "=r"(r[3]) : "r"(addr));
}
__device__ __forceinline__ void mma16816(float d[4], const uint32_t a[4], const uint32_t b0,
                                         const uint32_t b1) {
    asm volatile("mma.sync.aligned.m16n8k16.row.col.f32.bf16.bf16.f32 "
                 "{%0,%1,%2,%3},{%4,%5,%6,%7},{%8,%9},{%0,%1,%2,%3};"
                 : "+f"(d[0]), "+f"(d[1]), "+f"(d[2]), "+f"(d[3])
                 : "r"(a[0]), "r"(a[1]), "r"(a[2]), "r"(a[3]), "r"(b0), "r"(b1));
}
__device__ __forceinline__ void mma16816h(float d[4], const uint32_t a[4], const uint32_t b0,
                                          const uint32_t b1) {
    asm volatile("mma.sync.aligned.m16n8k16.row.col.f32.f16.f16.f32 "
                 "{%0,%1,%2,%3},{%4,%5,%6,%7},{%8,%9},{%0,%1,%2,%3};"
                 : "+f"(d[0]), "+f"(d[1]), "+f"(d[2]), "+f"(d[3])
                 : "r"(a[0]), "r"(a[1]), "r"(a[2]), "r"(a[3]), "r"(b0), "r"(b1));
}
__device__ __forceinline__ uint32_t packsplit(float v0, float v1, uint32_t& lo) {
    __nv_bfloat16 h0 = __float2bfloat16(v0), h1 = __float2bfloat16(v1);
    __nv_bfloat16 l0 = __float2bfloat16(v0 - __bfloat162float(h0));
    __nv_bfloat16 l1 = __float2bfloat16(v1 - __bfloat162float(h1));
    lo = (uint32_t)__bfloat16_as_ushort(l0) | ((uint32_t)__bfloat16_as_ushort(l1) << 16);
    return (uint32_t)__bfloat16_as_ushort(h0) | ((uint32_t)__bfloat16_as_ushort(h1) << 16);
}
__device__ __forceinline__ uint32_t packh2(float a, float b) {
    __half2 h = __floats2half2_rn(a, b);
    return *(uint32_t*)&h;
}
#define CP_ASYNC16(s, g) asm volatile("cp.async.cg.shared.global [%0], [%1], 16;" ::"r"(s), "l"(g) : "memory")
#define CP_COMMIT() asm volatile("cp.async.commit_group;" ::: "memory")
#define CP_WAIT1() asm volatile("cp.async.wait_group 1;" ::: "memory")
#define CP_WAIT0() asm volatile("cp.async.wait_group 0;" ::: "memory")

// -------- scratch --------
static __device__ float g_om[NB * 27 * HWX];
static __device__ __align__(16) __half g_xth[NB * HWX * CINX];
static __device__ __align__(16) __half g_out1th[NB * HWX * NCO];
static __device__ __align__(16) __half g_o2h[NB * NCO * 16384];
static __device__ float g_stats1[2 * NCO];
static __device__ float g_stats2[2 * NCO];
static __device__ float g_p1[256 * 128 * 2];
static __device__ float g_p2[2048 * 128 * 2];
static __device__ __align__(16) __nv_bfloat16 g_k1Ahi[36 * 2304], g_k1Alo[36 * 2304];
static __device__ __align__(16) __half g_k2Ah[36 * 9216];
static __device__ __align__(16) __half g_k4Ah[32 * 9216];

// -------- K0: weight prep --------
__global__ void k0_prep(const float* __restrict__ w_dcn, const float* __restrict__ w_off,
                        const float* __restrict__ w_ct) {
    const int N_K1 = 36 * 2048, N_K2 = 128 * 256 * 9, N_K4 = 262144;
    const int ntot = N_K1 + N_K2 + N_K4;
    for (int idx = blockIdx.x * blockDim.x + threadIdx.x; idx < ntot; idx += gridDim.x * blockDim.x) {
        if (idx < N_K1) {
            const int st = idx >> 11, o = (idx >> 6) & 31, kk = idx & 63;
            const int c = (st & 3) * 64 + kk, j = st >> 2;
            const float w = (o < 27) ? w_off[(o * CINX + c) * 9 + j] : 0.f;
            const __nv_bfloat16 hi = __float2bfloat16(w);
            g_k1Ahi[st * 2304 + o * 72 + kk] = hi;
            g_k1Alo[st * 2304 + o * 72 + kk] = __float2bfloat16(w - __bfloat162float(hi));
        } else if (idx < N_K1 + N_K2) {
            const int r = idx - N_K1, o = r & 127, c = (r >> 7) & 255, k = r >> 15;
            const float w = w_dcn[(o * CINX + c) * 9 + k];
            const int st = r >> 13, kk = (r >> 7) & 63;
            g_k2Ah[st * 9216 + o * 72 + kk] = __float2half(w);
        } else {
            const int r2 = idx - N_K1 - N_K2;
            const int o = r2 & 127, c = (r2 >> 7) & 127, j = (r2 >> 14) & 7, P = r2 >> 17;
            const int wdh = P + 2 * (j >> 2), wdw = j & 3;
            const float w = w_ct[(c * NCO + o) * 16 + (3 - wdh) * 4 + (3 - wdw)];
            const int st = j * 2 + (c >> 6), kk = c & 63;
            g_k4Ah[(P * 16 + st) * 9216 + o * 72 + kk] = __float2half(w);
        }
    }
}

// -------- kT: x NCHW -> NHWC half --------
__global__ void kT_transpose(const float* __restrict__ x) {
    __shared__ float tile[32][33];
    const int b = blockIdx.z;
    const int cb = blockIdx.y * 32, hb = blockIdx.x * 32;
    const int tx = threadIdx.x & 31, ty = threadIdx.x >> 5;
    const float* xb = x + ((size_t)b * CINX + cb) * HWX + hb;
#pragma unroll
    for (int i = 0; i < 32; i += 8) tile[ty + i][tx] = xb[(size_t)(ty + i) * HWX + tx];
    __syncthreads();
    __half* xoh = g_xth + ((size_t)b * HWX + hb) * CINX + cb;
#pragma unroll
    for (int i = 0; i < 32; i += 8)
        xoh[(size_t)(ty + i) * CINX + tx] = __float2half(tile[tx][ty + i]);
}

// -------- K1: offset conv, bf16x3 math, half-input gather --------
#define K1_SMEM 55296
__global__ __launch_bounds__(256) void k1_off_mma(const float* __restrict__ b_off) {
    extern __shared__ char sm[];
    const uint32_t sb = smem_u32(sm);
    const int b = blockIdx.x >> 6, h = blockIdx.x & 63, t = threadIdx.x;
    const int px = t >> 2, qq = t & 3;
    const int w = t >> 5, L = t & 31;
    const int m0 = (w & 1) * 16, n0 = (w >> 1) * 16;
    const uint32_t aAb = sb + (m0 + (L & 15)) * 144 + ((L & 16) ? 16 : 0);
    const uint32_t aBb = sb + 18432 + (n0 + (L & 7) + ((L & 16) ? 8 : 0)) * 144 + ((L & 8) ? 16 : 0);
    const __half* xtb = g_xth + (size_t)b * HWX * CINX;

    float acc[2][4];
#pragma unroll
    for (int i = 0; i < 2; i++)
#pragma unroll
        for (int q = 0; q < 4; q++) acc[i][q] = 0.f;

    uint4 ra, rb;
    bool rok;
    {
        const uint4* gh = (const uint4*)g_k1Ahi;
        const uint4* gl = (const uint4*)g_k1Alo;
        for (int i = t; i < 288; i += 256) {
            CP_ASYNC16(sb + i * 16, gh + i);
            CP_ASYNC16(sb + 4608 + i * 16, gl + i);
        }
        CP_COMMIT();
        const int row = h - 1, col = px - 1;
        rok = (row >= 0) && (col >= 0) && (col < WWD);
        if (rok) {
            const uint4* sp = (const uint4*)(xtb + ((size_t)row * 64 + col) * CINX + qq * 16);
            ra = sp[0]; rb = sp[1];
        }
    }

    for (int s = 0; s < 36; ++s) {
        const int buf = s & 1;
        {
            float v[16];
            if (rok) {
                const __half2* pa = (const __half2*)&ra;
                const __half2* pb = (const __half2*)&rb;
#pragma unroll
                for (int i = 0; i < 4; i++) {
                    const float2 f = __half22float2(pa[i]);
                    v[2 * i] = f.x; v[2 * i + 1] = f.y;
                }
#pragma unroll
                for (int i = 0; i < 4; i++) {
                    const float2 f = __half22float2(pb[i]);
                    v[8 + 2 * i] = f.x; v[8 + 2 * i + 1] = f.y;
                }
            } else {
#pragma unroll
                for (int z = 0; z < 16; z++) v[z] = 0.f;
            }
            uint32_t hw_[8], lw_[8];
#pragma unroll
            for (int i = 0; i < 8; i++) hw_[i] = packsplit(v[2 * i], v[2 * i + 1], lw_[i]);
            char* Bp = sm + 18432 + buf * 18432 + px * 144 + qq * 32;
            ((uint4*)Bp)[0] = make_uint4(hw_[0], hw_[1], hw_[2], hw_[3]);
            ((uint4*)Bp)[1] = make_uint4(hw_[4], hw_[5], hw_[6], hw_[7]);
            ((uint4*)(Bp + 9216))[0] = make_uint4(lw_[0], lw_[1], lw_[2], lw_[3]);
            ((uint4*)(Bp + 9216))[1] = make_uint4(lw_[4], lw_[5], lw_[6], lw_[7]);
        }
        __syncthreads();
        const bool more = (s + 1 < 36);
        if (more) {
            const int sn = s + 1;
            const uint4* gh = ((const uint4*)g_k1Ahi) + sn * 288;
            const uint4* gl = ((const uint4*)g_k1Alo) + sn * 288;
            const uint32_t dA = sb + (sn & 1) * 9216;
            for (int i = t; i < 288; i += 256) {
                CP_ASYNC16(dA + i * 16, gh + i);
                CP_ASYNC16(dA + 4608 + i * 16, gl + i);
            }
            CP_COMMIT();
            CP_WAIT1();
            const int j = sn >> 2, c0 = (sn & 3) * 64;
            const int jy = j / 3, jx = j - jy * 3;
            const int row = h - 1 + jy, col = px - 1 + jx;
            rok = (row >= 0) && (row < HH) && (col >= 0) && (col < WWD);
            if (rok) {
                const uint4* sp = (const uint4*)(xtb + ((size_t)row * 64 + col) * CINX + c0 + qq * 16);
                ra = sp[0]; rb = sp[1];
            }
        } else {
            CP_WAIT0();
        }
        const uint32_t aA = aAb + buf * 9216;
        const uint32_t aB = aBb + buf * 18432;
#pragma unroll
        for (int ks = 0; ks < 4; ks++) {
            const uint32_t kb = ks * 32;
            uint32_t ah[4], al[4], bh[4], bl[4];
            ldsm4(aA + kb, ah);
            ldsm4(aA + 4608 + kb, al);
            ldsm4(aB + kb, bh);
            ldsm4(aB + 9216 + kb, bl);
#pragma unroll
            for (int tn = 0; tn < 2; tn++) {
                mma16816(acc[tn], ah, bh[tn * 2], bh[tn * 2 + 1]);
                mma16816(acc[tn], ah, bl[tn * 2], bl[tn * 2 + 1]);
                mma16816(acc[tn], al, bh[tn * 2], bh[tn * 2 + 1]);
            }
        }
    }
    const int o = m0 + (L >> 2);
#pragma unroll
    for (int tn = 0; tn < 2; tn++) {
        const int pc = n0 + tn * 8 + (L & 3) * 2;
        if (o < 27) {
            const float bv = b_off[o];
            float2 v = {acc[tn][0] + bv, acc[tn][1] + bv};
            *(float2*)(g_om + (((size_t)b * 27 + o) * 64 + h) * 64 + pc) = v;
        }
        if (o + 8 < 27) {
            const float bv = b_off[o + 8];
            float2 v = {acc[tn][2] + bv, acc[tn][3] + bv};
            *(float2*)(g_om + (((size_t)b * 27 + o + 8) * 64 + h) * 64 + pc) = v;
        }
    }
}

// -------- K2: DCN, fp16 gather, M128xN128, 512 threads (R11-proven) --------
#define K2_SMEM 73728
__device__ __forceinline__ void bilin2(int b, int row, int col, int T, int* pidx, float* pwgt) {
    const float oy = g_om[((b * 27 + T) * 64 + row) * 64 + col];
    const float ox = g_om[((b * 27 + 9 + T) * 64 + row) * 64 + col];
    const float mm = g_om[((b * 27 + 18 + T) * 64 + row) * 64 + col];
    const float mask = 1.0f / (1.0f + expf(-mm));
    const float py = oy + (float)(row - 1 + T / 3);
    const float pxx = ox + (float)(col - 1 + T % 3);
    const float y0f = floorf(py), x0f = floorf(pxx);
    const int y0 = (int)y0f, x0 = (int)x0f;
    const float ly = py - y0f, lx = pxx - x0f;
#pragma unroll
    for (int q = 0; q < 4; q++) {
        const int yi = y0 + (q >> 1), xi = x0 + (q & 1);
        const bool valid = (yi >= 0) && (yi < HH) && (xi >= 0) && (xi < WWD);
        pidx[q] = min(max(yi, 0), HH - 1) * WWD + min(max(xi, 0), WWD - 1);
        const float wq = ((q >> 1) ? ly : 1.f - ly) * ((q & 1) ? lx : 1.f - lx);
        pwgt[q] = valid ? wq * mask : 0.f;
    }
}
__device__ __forceinline__ void acc_h16(float* v, uint4 ha, uint4 hb, float wq) {
    const __half2* pa = (const __half2*)&ha;
    const __half2* pb = (const __half2*)&hb;
#pragma unroll
    for (int i = 0; i < 4; i++) {
        const float2 f = __half22float2(pa[i]);
        v[2 * i] += wq * f.x; v[2 * i + 1] += wq * f.y;
    }
#pragma unroll
    for (int i = 0; i < 4; i++) {
        const float2 f = __half22float2(pb[i]);
        v[8 + 2 * i] += wq * f.x; v[8 + 2 * i + 1] += wq * f.y;
    }
}

__global__ __launch_bounds__(512, 1) void k2_dcn_mma(const float* __restrict__ b_dcn) {
    extern __shared__ char sm[];
    const uint32_t sb = smem_u32(sm);
    const int b = blockIdx.x >> 5, H = blockIdx.x & 31, t = threadIdx.x;
    const __half* xtb = g_xth + (size_t)b * HWX * CINX;
    const int px = t >> 2, qq = t & 3;
    const int row = 2 * H + (px >> 6), col = px & 63;
    const int w = t >> 5, L = t & 31;
    const int m0 = (w & 3) * 32, n0 = (w >> 2) * 32;
    const uint32_t aAb = sb + (m0 + (L & 15)) * 144 + ((L & 16) ? 16 : 0);
    const uint32_t aBb = sb + 36864 + (n0 + (L & 7) + ((L & 16) ? 8 : 0)) * 144 + ((L & 8) ? 16 : 0);

    float acc[2][4][4];
#pragma unroll
    for (int i = 0; i < 2; i++)
#pragma unroll
        for (int j = 0; j < 4; j++)
#pragma unroll
            for (int q = 0; q < 4; q++) acc[i][j][q] = 0.f;

    int pidx[4];
    float pwgt[4];
    float v[16];
    {
        const uint4* gh = (const uint4*)g_k2Ah;
        for (int i = t; i < 1152; i += 512) CP_ASYNC16(sb + i * 16, gh + i);
        CP_COMMIT();
        bilin2(b, row, col, 0, pidx, pwgt);
#pragma unroll
        for (int i = 0; i < 16; i++) v[i] = 0.f;
#pragma unroll
        for (int cn = 0; cn < 4; cn++) {
            const uint4* sp = (const uint4*)(xtb + (size_t)pidx[cn] * CINX + qq * 16);
            acc_h16(v, sp[0], sp[1], pwgt[cn]);
        }
    }

    for (int s = 0; s < 36; ++s) {
        const int buf = s & 1;
        {
            uint32_t hw_[8];
#pragma unroll
            for (int i = 0; i < 8; i++) hw_[i] = packh2(v[2 * i], v[2 * i + 1]);
            char* Bp = sm + 36864 + buf * 18432 + px * 144 + qq * 32;
            ((uint4*)Bp)[0] = make_uint4(hw_[0], hw_[1], hw_[2], hw_[3]);
            ((uint4*)Bp)[1] = make_uint4(hw_[4], hw_[5], hw_[6], hw_[7]);
        }
        __syncthreads();
        const bool more = (s + 1 < 36);
        const __half* gbase = xtb;
        if (more) {
            const uint4* gh = ((const uint4*)g_k2Ah) + (s + 1) * 1152;
            const uint32_t dA = sb + ((s + 1) & 1) * 18432;
            for (int i = t; i < 1152; i += 512) CP_ASYNC16(dA + i * 16, gh + i);
            CP_COMMIT();
            CP_WAIT1();
            if (((s + 1) & 3) == 0) bilin2(b, row, col, (s + 1) >> 2, pidx, pwgt);
            gbase = xtb + ((s + 1) & 3) * 64 + qq * 16;
#pragma unroll
            for (int i = 0; i < 16; i++) v[i] = 0.f;
        } else {
            CP_WAIT0();
        }
        const uint32_t aA = aAb + buf * 18432;
        const uint32_t aB = aBb + buf * 18432;
        uint4 ra, rb;
        if (more) {
            const uint4* sp = (const uint4*)(gbase + (size_t)pidx[0] * CINX);
            ra = sp[0]; rb = sp[1];
        }
#pragma unroll
        for (int ks = 0; ks < 4; ks++) {
            const uint32_t kb = ks * 32;
            uint32_t ah[2][4], bh[2][4];
            ldsm4(aA + kb, ah[0]);
            ldsm4(aA + 2304 + kb, ah[1]);
            ldsm4(aB + kb, bh[0]);
            ldsm4(aB + 2304 + kb, bh[1]);
#pragma unroll
            for (int tm = 0; tm < 2; tm++)
#pragma unroll
                for (int tn = 0; tn < 4; tn++) {
                    const uint32_t* BH = &bh[tn >> 1][(tn & 1) * 2];
                    mma16816h(acc[tm][tn], ah[tm], BH[0], BH[1]);
                }
            if (more) {
                acc_h16(v, ra, rb, pwgt[ks]);
                if (ks < 3) {
                    const uint4* sp = (const uint4*)(gbase + (size_t)pidx[ks + 1] * CINX);
                    ra = sp[0]; rb = sp[1];
                }
            }
        }
    }
    // epilogue: half NHWC out1t + BN1 partials
    float* red = (float*)(sm + 36864);
    const int ng = w >> 2;
#pragma unroll
    for (int tm = 0; tm < 2; tm++) {
        const int o = m0 + tm * 16 + (L >> 2);
        const float bv0 = b_dcn[o], bv1 = b_dcn[o + 8];
        float so = 0.f, qo = 0.f, s8 = 0.f, q8 = 0.f;
#pragma unroll
        for (int tn = 0; tn < 4; tn++) {
            const int pc = n0 + tn * 8 + (L & 3) * 2;
            __half* base = g_out1th + ((size_t)b * HWX + H * 128 + pc) * NCO + o;
            const float v0 = acc[tm][tn][0] + bv0, v1 = acc[tm][tn][1] + bv0;
            const float v2 = acc[tm][tn][2] + bv1, v3 = acc[tm][tn][3] + bv1;
            base[0] = __float2half(v0); base[NCO] = __float2half(v1);
            base[8] = __float2half(v2); base[NCO + 8] = __float2half(v3);
            so += v0 + v1; qo += v0 * v0 + v1 * v1;
            s8 += v2 + v3; q8 += v2 * v2 + v3 * v3;
        }
#pragma unroll
        for (int d = 1; d < 4; d <<= 1) {
            so += __shfl_xor_sync(0xFFFFFFFF, so, d);
            qo += __shfl_xor_sync(0xFFFFFFFF, qo, d);
            s8 += __shfl_xor_sync(0xFFFFFFFF, s8, d);
            q8 += __shfl_xor_sync(0xFFFFFFFF, q8, d);
        }
        if ((L & 3) == 0) {
            red[(ng * 128 + o) * 2] = so;
            red[(ng * 128 + o) * 2 + 1] = qo;
            red[(ng * 128 + o + 8) * 2] = s8;
            red[(ng * 128 + o + 8) * 2 + 1] = q8;
        }
    }
    __syncthreads();
    if (t < 128) {
        float ss = 0.f, qs = 0.f;
#pragma unroll
        for (int g = 0; g < 4; g++) {
            ss += red[(g * 128 + t) * 2];
            qs += red[(g * 128 + t) * 2 + 1];
        }
        g_p1[(blockIdx.x * 128 + t) * 2] = ss;
        g_p1[(blockIdx.x * 128 + t) * 2 + 1] = qs;
    }
}

// -------- BN finalize --------
__device__ __forceinline__ void fin_body(const float* part, int nblk, float nelem,
                                         const float* gamma, const float* beta, float* stats) {
    const int ch = blockIdx.x, t = threadIdx.x;
    float s = 0.f, q = 0.f;
    for (int i = t; i < nblk; i += 256) {
        s += part[(i * 128 + ch) * 2];
        q += part[(i * 128 + ch) * 2 + 1];
    }
    __shared__ float rs[256], rq[256];
    rs[t] = s; rq[t] = q;
    __syncthreads();
    for (int off = 128; off > 0; off >>= 1) {
        if (t < off) { rs[t] += rs[t + off]; rq[t] += rq[t + off]; }
        __syncthreads();
    }
    if (t == 0) {
        const float mean = rs[0] / nelem;
        const float var = rq[0] / nelem - mean * mean;
        const float sc = rsqrtf(var + EPSV) * gamma[ch];
        stats[ch] = sc;
        stats[NCO + ch] = beta[ch] - mean * sc;
    }
}
__global__ void k3b_fin(const float* __restrict__ g, const float* __restrict__ b) {
    fin_body(g_p1, 256, (float)(NB * HWX), g, b, g_stats1);
}
__global__ void k5b_fin(const float* __restrict__ g, const float* __restrict__ b) {
    fin_body(g_p2, 2048, (float)(NB * 16384), g, b, g_stats2);
}

// -------- K4: tconv, fp16, parity-split (R11-proven), half output --------
// smem: A0@0, A1@18432, B0@36864, B1@46080, sStats@55296 (1024). total 56320.
#define K4_SMEM 56320
__device__ __forceinline__ int k4_st(int s, int p) {
    const int r = s >> 2, dwi = (s >> 1) & 1, ch = s & 1;
    return (r * 4 + p + 2 * dwi) * 2 + ch;
}
__global__ __launch_bounds__(256, 2) void k4_tconv_mma() {
    extern __shared__ char sm[];
    const uint32_t sb = smem_u32(sm);
    const int b = blockIdx.x >> 8, Y = (blockIdx.x >> 1) & 127, p = blockIdx.x & 1;
    const int t = threadIdx.x, Ypar = Y & 1, y0r = (Y - 2 + Ypar) / 2;
    float* sStats = (float*)(sm + 55296);
    const int ii = t >> 2, qq = t & 3;
    const int w = t >> 5, L = t & 31;
    const int m0 = (w & 3) * 32, n0 = (w >> 2) * 32;
    const uint32_t aAb = sb + (m0 + (L & 15)) * 144 + ((L & 16) ? 16 : 0);
    const uint32_t aBb = sb + 36864 + (n0 + (L & 7) + ((L & 16) ? 8 : 0)) * 144 + ((L & 8) ? 16 : 0);

    sStats[t] = g_stats1[t];

    float acc[2][4][4];
#pragma unroll
    for (int i = 0; i < 2; i++)
#pragma unroll
        for (int j = 0; j < 4; j++)
#pragma unroll
            for (int q = 0; q < 4; q++) acc[i][j][q] = 0.f;

    uint4 ra, rb;
    bool rok;
    int rcnx;
    {
        const int st0 = k4_st(0, p);
        const uint4* gh = ((const uint4*)g_k4Ah) + (Ypar * 16 + st0) * 1152;
        for (int i = t; i < 1152; i += 256) CP_ASYNC16(sb + i * 16, gh + i);
        CP_COMMIT();
        const int yrow = y0r, gx = ii + p - 1;
        rcnx = qq * 16;
        rok = (yrow >= 0) && (yrow < HH) && (gx >= 0) && (gx < WWD);
        if (rok) {
            const uint4* sp = (const uint4*)(g_out1th + ((size_t)b * HWX + yrow * 64 + gx) * NCO + rcnx);
            ra = sp[0]; rb = sp[1];
        }
    }
    __syncthreads();  // sStats visible

    for (int s = 0; s < 8; ++s) {
        const int buf = s & 1;
        {
            float v[16];
            if (rok) {
                const __half2* pa = (const __half2*)&ra;
                const __half2* pb = (const __half2*)&rb;
#pragma unroll
                for (int j2 = 0; j2 < 4; j2++) {
                    const float2 f = __half22float2(pa[j2]);
                    const int c = rcnx + j2 * 2;
                    v[j2 * 2 + 0] = fmaxf(0.f, fmaf(f.x, sStats[c + 0], sStats[128 + c + 0]));
                    v[j2 * 2 + 1] = fmaxf(0.f, fmaf(f.y, sStats[c + 1], sStats[128 + c + 1]));
                }
#pragma unroll
                for (int j2 = 0; j2 < 4; j2++) {
                    const float2 f = __half22float2(pb[j2]);
                    const int c = rcnx + 8 + j2 * 2;
                    v[8 + j2 * 2 + 0] = fmaxf(0.f, fmaf(f.x, sStats[c + 0], sStats[128 + c + 0]));
                    v[8 + j2 * 2 + 1] = fmaxf(0.f, fmaf(f.y, sStats[c + 1], sStats[128 + c + 1]));
                }
            } else {
#pragma unroll
                for (int z = 0; z < 16; z++) v[z] = 0.f;
            }
            uint32_t hw_[8];
#pragma unroll
            for (int i = 0; i < 8; i++) hw_[i] = packh2(v[2 * i], v[2 * i + 1]);
            char* Bp = sm + 36864 + buf * 9216 + ii * 144 + qq * 32;
            ((uint4*)Bp)[0] = make_uint4(hw_[0], hw_[1], hw_[2], hw_[3]);
            ((uint4*)Bp)[1] = make_uint4(hw_[4], hw_[5], hw_[6], hw_[7]);
        }
        __syncthreads();
        const bool more = (s + 1 < 8);
        if (more) {
            const int stn = k4_st(s + 1, p);
            const uint4* gh = ((const uint4*)g_k4Ah) + (Ypar * 16 + stn) * 1152;
            const uint32_t dA = sb + ((s + 1) & 1) * 18432;
            for (int i = t; i < 1152; i += 256) CP_ASYNC16(dA + i * 16, gh + i);
            CP_COMMIT();
            CP_WAIT1();
            const int sn = s + 1;
            const int r = sn >> 2, dwi = (sn >> 1) & 1, ch = sn & 1;
            const int yrow = y0r + r, gx = ii + p + dwi - 1;
            rcnx = ch * 64 + qq * 16;
            rok = (yrow >= 0) && (yrow < HH) && (gx >= 0) && (gx < WWD);
            if (rok) {
                const uint4* sp = (const uint4*)(g_out1th + ((size_t)b * HWX + yrow * 64 + gx) * NCO + rcnx);
                ra = sp[0]; rb = sp[1];
            }
        } else {
            CP_WAIT0();
        }
        const uint32_t aA = aAb + buf * 18432;
        const uint32_t aB = aBb + buf * 9216;
#pragma unroll
        for (int ks = 0; ks < 4; ks++) {
            const uint32_t kb = ks * 32;
            uint32_t ah[2][4], bh[2][4];
            ldsm4(aA + kb, ah[0]);
            ldsm4(aA + 2304 + kb, ah[1]);
            ldsm4(aB + kb, bh[0]);
            ldsm4(aB + 2304 + kb, bh[1]);
#pragma unroll
            for (int tm = 0; tm < 2; tm++)
#pragma unroll
                for (int tn = 0; tn < 4; tn++) {
                    const uint32_t* BH = &bh[tn >> 1][(tn & 1) * 2];
                    mma16816h(acc[tm][tn], ah[tm], BH[0], BH[1]);
                }
        }
    }
    // epilogue: write half out2 scratch + BN2 partials (from fp32 accs)
    float* red = (float*)(sm + 36864);
    const int ng = w >> 2;
#pragma unroll
    for (int tm = 0; tm < 2; tm++) {
        const int o = m0 + tm * 16 + (L >> 2);
        float so = 0.f, qo = 0.f, s8 = 0.f, q8 = 0.f;
#pragma unroll
        for (int tn = 0; tn < 4; tn++) {
            const int ic = n0 + tn * 8 + (L & 3) * 2;
            const int X = 2 * ic + p;
            __half* base = g_o2h + (((size_t)b * NCO + o) * 128 + Y) * 128 + X;
            const float v0 = acc[tm][tn][0], v1 = acc[tm][tn][1];
            const float v2 = acc[tm][tn][2], v3 = acc[tm][tn][3];
            base[0] = __float2half(v0); base[2] = __float2half(v1);
            base[8 * 16384] = __float2half(v2); base[8 * 16384 + 2] = __float2half(v3);
            so += v0 + v1; qo += v0 * v0 + v1 * v1;
            s8 += v2 + v3; q8 += v2 * v2 + v3 * v3;
        }
#pragma unroll
        for (int d = 1; d < 4; d <<= 1) {
            so += __shfl_xor_sync(0xFFFFFFFF, so, d);
            qo += __shfl_xor_sync(0xFFFFFFFF, qo, d);
            s8 += __shfl_xor_sync(0xFFFFFFFF, s8, d);
            q8 += __shfl_xor_sync(0xFFFFFFFF, q8, d);
        }
        if ((L & 3) == 0) {
            red[(ng * 128 + o) * 2] = so;
            red[(ng * 128 + o) * 2 + 1] = qo;
            red[(ng * 128 + o + 8) * 2] = s8;
            red[(ng * 128 + o + 8) * 2 + 1] = q8;
        }
    }
    __syncthreads();
    if (t < 128) {
        g_p2[(blockIdx.x * 128 + t) * 2] = red[t * 2] + red[(128 + t) * 2];
        g_p2[(blockIdx.x * 128 + t) * 2 + 1] = red[t * 2 + 1] + red[(128 + t) * 2 + 1];
    }
}

// -------- K6: BN2+ReLU (read half scratch, write fp32 out) --------
__global__ void k6_bnrelu(float* __restrict__ out) {
    const int n4 = NB * NCO * 128 * 128 / 4;
    int i4 = blockIdx.x * blockDim.x + threadIdx.x;
    if (i4 < n4) {
        const uint2 hv = ((const uint2*)g_o2h)[i4];
        const __half2* ph = (const __half2*)&hv;
        const float2 f0 = __half22float2(ph[0]);
        const float2 f1 = __half22float2(ph[1]);
        const int ch = (i4 >> 12) & 127;
        const float sc = g_stats2[ch], sh = g_stats2[NCO + ch];
        float4 v;
        v.x = fmaxf(0.f, fmaf(f0.x, sc, sh));
        v.y = fmaxf(0.f, fmaf(f0.y, sc, sh));
        v.z = fmaxf(0.f, fmaf(f1.x, sc, sh));
        v.w = fmaxf(0.f, fmaf(f1.y, sc, sh));
        ((float4*)out)[i4] = v;
    }
}

extern "C" void kernel_launch(void* const* d_in, const int* in_sizes, int n_in,
                              void* d_out, int out_size) {
    const float* x = (const float*)d_in[0];
    const float* w_off = (const float*)d_in[1];
    const float* b_off = (const float*)d_in[2];
    const float* w_dcn = (const float*)d_in[3];
    const float* b_dcn = (const float*)d_in[4];
    const float* gamma1 = (const float*)d_in[5];
    const float* beta1 = (const float*)d_in[6];
    const float* w_ct = (const float*)d_in[7];
    const float* gamma2 = (const float*)d_in[8];
    const float* beta2 = (const float*)d_in[9];
    float* out = (float*)d_out;
    (void)in_sizes; (void)n_in; (void)out_size;

    static int attr_done = 0;
    if (!attr_done) {
        cudaFuncSetAttribute(k1_off_mma, cudaFuncAttributeMaxDynamicSharedMemorySize, K1_SMEM);
        cudaFuncSetAttribute(k2_dcn_mma, cudaFuncAttributeMaxDynamicSharedMemorySize, K2_SMEM);
        cudaFuncSetAttribute(k4_tconv_mma, cudaFuncAttributeMaxDynamicSharedMemorySize, K4_SMEM);
        attr_done = 1;
    }
    k0_prep<<<256, 256>>>(w_dcn, w_off, w_ct);
    kT_transpose<<<dim3(128, 8, 8), 256>>>(x);
    k1_off_mma<<<NB * HH, 256, K1_SMEM>>>(b_off);
    k2_dcn_mma<<<NB * 32, 512, K2_SMEM>>>(b_dcn);
    k3b_fin<<<NCO, 256>>>(gamma1, beta1);
    k4_tconv_mma<<<NB * 128 * 2, 256, K4_SMEM>>>();
    k5b_fin<<<NCO, 256>>>(gamma2, beta2);
    k6_bnrelu<<<(NB * NCO * 128 * 128 / 4 + 255) / 256, 256>>>(out);
}